// round 1
// baseline (speedup 1.0000x reference)
#include <cuda_runtime.h>
#include <cstdint>
#include <math.h>

// Problem constants
#define Bv    2048
#define Dv    1024
#define Hv    8
#define HDv   128
#define Fv    4096
#define Lv    2
#define Mclip 256
#define MEMv  16
#define Sv    17
#define STOv  1024
#define ACTv  32
#define HIDv  1024
#define NTOK  (Bv*Sv)       // 34816
#define TOKC  (STOv+ACTv)   // 1056
#define EPSv  1e-4f
#define SCALEv 0.08838834764831845f  // 128^-0.5

// ---------------- scratch (static device memory; no allocations) -----------
__device__ float g_tokcat[Bv*TOKC];
__device__ float g_hid[Bv*HIDv];
__device__ float g_seq[NTOK*Dv];
__device__ float g_xn [NTOK*Dv];
__device__ float g_q  [NTOK*Dv];
__device__ float g_k  [NTOK*Dv];
__device__ float g_v  [NTOK*Dv];
__device__ float g_att[NTOK*Dv];
__device__ float g_ff [(size_t)NTOK*Fv];

// ---------------- helpers ---------------------------------------------------
__device__ __forceinline__ float f2tf32(float x){
    uint32_t u;
    asm("cvt.rna.tf32.f32 %0, %1;" : "=r"(u) : "f"(x));
    return __uint_as_float(u);
}

__device__ __forceinline__ void mma8(float c[4], const uint32_t a[4], const uint32_t b[2]){
    asm volatile(
        "mma.sync.aligned.m16n8k8.row.col.f32.tf32.tf32.f32 "
        "{%0,%1,%2,%3}, {%4,%5,%6,%7}, {%8,%9}, {%0,%1,%2,%3};\n"
        : "+f"(c[0]), "+f"(c[1]), "+f"(c[2]), "+f"(c[3])
        : "r"(a[0]), "r"(a[1]), "r"(a[2]), "r"(a[3]), "r"(b[0]), "r"(b[1]));
}

__device__ __forceinline__ float block_reduce_sum_256(float val){
    __shared__ float sh[8];
    __shared__ float tot;
    int lane = threadIdx.x & 31, wid = threadIdx.x >> 5;
    #pragma unroll
    for (int o = 16; o; o >>= 1) val += __shfl_xor_sync(0xffffffffu, val, o);
    if (lane == 0) sh[wid] = val;
    __syncthreads();
    if (wid == 0){
        float v = (lane < 8) ? sh[lane] : 0.f;
        #pragma unroll
        for (int o = 4; o; o >>= 1) v += __shfl_xor_sync(0xffffffffu, v, o);
        if (lane == 0) tot = v;
    }
    __syncthreads();
    return tot;
}

// ---------------- tf32 GEMM: C[M,N] = act(A[M,K] @ W[K,N] + bias) + res -----
// act: 0 = none, 2 = exact gelu. BM=BN=128, BK=32, 128 threads, 64x64 warp tiles.
#define BMt 128
#define BNt 128
#define BKt 32

__global__ void __launch_bounds__(128, 2) gemm_tf32(
    const float* __restrict__ A, const float* __restrict__ W,
    const float* __restrict__ bias, const float* __restrict__ res,
    float* __restrict__ C,
    int M, int N, int K, int lda, int ldc, int act)
{
    __shared__ float As[BMt][BKt+4];
    __shared__ float Bs[BKt][BNt+4];

    const int tid  = threadIdx.x;
    const int lane = tid & 31;
    const int warp = tid >> 5;
    const int wm   = (warp >> 1) * 64;
    const int wn   = (warp & 1) * 64;
    const int bm   = blockIdx.y * BMt;
    const int bn   = blockIdx.x * BNt;
    const int ar   = lane >> 2;   // 0..7
    const int ac   = lane & 3;    // 0..3

    float c[4][8][4];
    #pragma unroll
    for (int mi = 0; mi < 4; mi++)
        #pragma unroll
        for (int ni = 0; ni < 8; ni++)
            #pragma unroll
            for (int r = 0; r < 4; r++) c[mi][ni][r] = 0.f;

    const int m0 = tid >> 5;   // 0..3
    const int ka = tid & 31;   // 0..31
    const float* Ap = A + (size_t)bm * lda;

    for (int k0 = 0; k0 < K; k0 += BKt){
        #pragma unroll
        for (int i = 0; i < 32; i++){
            int m = m0 + i * 4;
            As[m][ka] = f2tf32(Ap[(size_t)m * lda + k0 + ka]);
        }
        #pragma unroll
        for (int i = 0; i < 32; i++){
            Bs[i][tid] = f2tf32(W[(size_t)(k0 + i) * N + bn + tid]);
        }
        __syncthreads();

        #pragma unroll
        for (int ks = 0; ks < BKt; ks += 8){
            uint32_t a[4][4], b[8][2];
            #pragma unroll
            for (int mi = 0; mi < 4; mi++){
                int rm = wm + mi * 16;
                a[mi][0] = __float_as_uint(As[rm + ar    ][ks + ac    ]);
                a[mi][1] = __float_as_uint(As[rm + ar + 8][ks + ac    ]);
                a[mi][2] = __float_as_uint(As[rm + ar    ][ks + ac + 4]);
                a[mi][3] = __float_as_uint(As[rm + ar + 8][ks + ac + 4]);
            }
            #pragma unroll
            for (int ni = 0; ni < 8; ni++){
                int cn = wn + ni * 8 + ar;
                b[ni][0] = __float_as_uint(Bs[ks + ac    ][cn]);
                b[ni][1] = __float_as_uint(Bs[ks + ac + 4][cn]);
            }
            #pragma unroll
            for (int mi = 0; mi < 4; mi++)
                #pragma unroll
                for (int ni = 0; ni < 8; ni++)
                    mma8(c[mi][ni], a[mi], b[ni]);
        }
        __syncthreads();
    }

    // epilogue
    #pragma unroll
    for (int mi = 0; mi < 4; mi++){
        #pragma unroll
        for (int ni = 0; ni < 8; ni++){
            int col = bn + wn + ni * 8 + ac * 2;
            float bx = bias ? bias[col]     : 0.f;
            float by = bias ? bias[col + 1] : 0.f;
            #pragma unroll
            for (int h = 0; h < 2; h++){
                int row = bm + wm + mi * 16 + ar + h * 8;
                float v0 = c[mi][ni][h * 2 + 0] + bx;
                float v1 = c[mi][ni][h * 2 + 1] + by;
                if (act == 2){
                    v0 = 0.5f * v0 * (1.0f + erff(v0 * 0.7071067811865475f));
                    v1 = 0.5f * v1 * (1.0f + erff(v1 * 0.7071067811865475f));
                }
                size_t o = (size_t)row * ldc + col;
                if (res){ v0 += res[o]; v1 += res[o + 1]; }
                *reinterpret_cast<float2*>(C + o) = make_float2(v0, v1);
            }
        }
    }
}

// ---------------- rmsnorm (D=1024), optional +add input, optional silu ------
__global__ void rmsnorm_k(const float* __restrict__ x, int ldx,
                          const float* __restrict__ add,
                          const float* __restrict__ w,
                          float* __restrict__ y, int mode)
{
    int row = blockIdx.x;
    const float* xr = x + (size_t)row * ldx;
    float v[4]; float ss = 0.f;
    #pragma unroll
    for (int i = 0; i < 4; i++){
        int idx = threadIdx.x + i * 256;
        float t = xr[idx];
        if (add) t += add[(size_t)row * Dv + idx];
        v[i] = t; ss += t * t;
    }
    ss = block_reduce_sum_256(ss);
    float scale = rsqrtf(ss * (1.0f / Dv) + EPSv);
    #pragma unroll
    for (int i = 0; i < 4; i++){
        int idx = threadIdx.x + i * 256;
        float o = v[i] * scale * w[idx];
        if (mode == 1) o = o / (1.0f + expf(-o));   // silu
        y[(size_t)row * Dv + idx] = o;
    }
}

// ---------------- attention: one block per (b,h), S=17, HD=128 --------------
__global__ void attn_k(const float* __restrict__ Q, const float* __restrict__ K,
                       const float* __restrict__ V, const float* __restrict__ rel,
                       float* __restrict__ O)
{
    __shared__ float qs[Sv][HDv], ks[Sv][HDv], vs[Sv][HDv], sc[Sv][Sv];
    int bh = blockIdx.x;
    int b = bh >> 3, h = bh & 7;
    size_t base = (size_t)b * Sv * Dv + (size_t)h * HDv;

    for (int e = threadIdx.x; e < Sv * HDv; e += 256){
        int s = e >> 7, d = e & 127;
        size_t g = base + (size_t)s * Dv + d;
        qs[s][d] = Q[g]; ks[s][d] = K[g]; vs[s][d] = V[g];
    }
    __syncthreads();

    int lane = threadIdx.x & 31, warp = threadIdx.x >> 5;
    for (int e = warp; e < Sv * Sv; e += 8){
        int i = e / Sv, j = e % Sv;
        float p = 0.f;
        #pragma unroll
        for (int d = lane; d < HDv; d += 32) p += qs[i][d] * ks[j][d];
        #pragma unroll
        for (int o = 16; o; o >>= 1) p += __shfl_xor_sync(0xffffffffu, p, o);
        if (lane == 0){
            int r = i - j + Mclip;
            sc[i][j] = p * SCALEv + rel[r * Hv + h];
        }
    }
    __syncthreads();

    if (threadIdx.x < Sv){
        int i = threadIdx.x;
        float m = -1e30f;
        #pragma unroll
        for (int j = 0; j < Sv; j++) m = fmaxf(m, sc[i][j]);
        float s = 0.f;
        #pragma unroll
        for (int j = 0; j < Sv; j++){ float e_ = expf(sc[i][j] - m); sc[i][j] = e_; s += e_; }
        float inv = 1.0f / s;
        #pragma unroll
        for (int j = 0; j < Sv; j++) sc[i][j] *= inv;
    }
    __syncthreads();

    for (int e = threadIdx.x; e < Sv * HDv; e += 256){
        int i = e >> 7, d = e & 127;
        float acc = 0.f;
        #pragma unroll
        for (int j = 0; j < Sv; j++) acc += sc[i][j] * vs[j][d];
        O[base + (size_t)i * Dv + d] = acc;
    }
}

// ---------------- small data-movement kernels -------------------------------
__global__ void tokcat_k(const float* __restrict__ stoch, const float* __restrict__ action,
                         float* __restrict__ out)
{
    int idx = blockIdx.x * blockDim.x + threadIdx.x;
    if (idx >= Bv * TOKC) return;
    int b = idx / TOKC, c = idx - b * TOKC;
    float v;
    if (c < STOv) v = stoch[(size_t)b * STOv + c];
    else { float a = action[(size_t)b * ACTv + (c - STOv)]; v = a / fmaxf(fabsf(a), 1.0f); }
    out[idx] = v;
}

__global__ void mem_in_k(const float* __restrict__ memory, float* __restrict__ seq)
{
    int idx = blockIdx.x * blockDim.x + threadIdx.x;
    if (idx >= Bv * MEMv * Dv) return;
    int b = idx / (MEMv * Dv);
    int r = idx - b * (MEMv * Dv);
    seq[(size_t)b * Sv * Dv + r] = memory[idx];
}

__global__ void mem_out_k(const float* __restrict__ seq, float* __restrict__ out)
{
    int idx = blockIdx.x * blockDim.x + threadIdx.x;
    if (idx >= Bv * MEMv * Dv) return;
    int b = idx / (MEMv * Dv);
    // new_mem = seq[:, 1:17, :]
    out[idx] = seq[(size_t)idx + (size_t)(b + 1) * Dv];
}

// ---------------- driver ----------------------------------------------------
extern "C" void kernel_launch(void* const* d_in, const int* in_sizes, int n_in,
                              void* d_out, int out_size)
{
    (void)in_sizes; (void)n_in; (void)out_size;
    const float* stoch   = (const float*)d_in[0];
    const float* deter   = (const float*)d_in[1];
    const float* action  = (const float*)d_in[2];
    const float* memory  = (const float*)d_in[3];
    const float* inp_w1  = (const float*)d_in[4];
    const float* inp_b1  = (const float*)d_in[5];
    const float* inp_nw  = (const float*)d_in[6];
    const float* inp_w2  = (const float*)d_in[7];
    const float* inp_b2  = (const float*)d_in[8];
    const float* Wq      = (const float*)d_in[9];
    const float* bq      = (const float*)d_in[10];
    const float* Wk      = (const float*)d_in[11];
    const float* bk      = (const float*)d_in[12];
    const float* Wv      = (const float*)d_in[13];
    const float* bv      = (const float*)d_in[14];
    const float* Wo      = (const float*)d_in[15];
    const float* bo      = (const float*)d_in[16];
    const float* rel_emb = (const float*)d_in[17];
    const float* n1w     = (const float*)d_in[18];
    const float* n2w     = (const float*)d_in[19];
    const float* ffw1    = (const float*)d_in[20];
    const float* ffb1    = (const float*)d_in[21];
    const float* ffw2    = (const float*)d_in[22];
    const float* ffb2    = (const float*)d_in[23];
    const float* fnw     = (const float*)d_in[24];
    float* out = (float*)d_out;

    float *p_tokcat, *p_hid, *p_seq, *p_xn, *p_q, *p_k, *p_v, *p_att, *p_ff;
    cudaGetSymbolAddress((void**)&p_tokcat, g_tokcat);
    cudaGetSymbolAddress((void**)&p_hid, g_hid);
    cudaGetSymbolAddress((void**)&p_seq, g_seq);
    cudaGetSymbolAddress((void**)&p_xn,  g_xn);
    cudaGetSymbolAddress((void**)&p_q,   g_q);
    cudaGetSymbolAddress((void**)&p_k,   g_k);
    cudaGetSymbolAddress((void**)&p_v,   g_v);
    cudaGetSymbolAddress((void**)&p_att, g_att);
    cudaGetSymbolAddress((void**)&p_ff,  g_ff);

    // prep: tokcat + memory -> seq[:, :16]
    tokcat_k<<<(Bv * TOKC + 255) / 256, 256>>>(stoch, action, p_tokcat);
    mem_in_k<<<(Bv * MEMv * Dv + 255) / 256, 256>>>(memory, p_seq);

    // input MLP
    dim3 gI(Dv / BNt, Bv / BMt);           // 8 x 16
    gemm_tf32<<<gI, 128>>>(p_tokcat, inp_w1, inp_b1, nullptr, p_hid,
                           Bv, HIDv, TOKC, TOKC, HIDv, 0);
    rmsnorm_k<<<Bv, 256>>>(p_hid, Dv, nullptr, inp_nw, p_hid, 1);   // rmsnorm + silu
    gemm_tf32<<<gI, 128>>>(p_hid, inp_w2, inp_b2, nullptr, p_seq + (size_t)MEMv * Dv,
                           Bv, Dv, HIDv, HIDv, Sv * Dv, 0);

    dim3 gP(Dv / BNt, NTOK / BMt);         // 8 x 272
    dim3 gF(Fv / BNt, NTOK / BMt);         // 32 x 272

    for (int l = 0; l < Lv; l++){
        const float* wq = Wq + (size_t)l * Dv * Dv;
        const float* wk = Wk + (size_t)l * Dv * Dv;
        const float* wv = Wv + (size_t)l * Dv * Dv;
        const float* wo = Wo + (size_t)l * Dv * Dv;
        const float* f1 = ffw1 + (size_t)l * Dv * Fv;
        const float* f2 = ffw2 + (size_t)l * Fv * Dv;

        rmsnorm_k<<<NTOK, 256>>>(p_seq, Dv, nullptr, n1w + l * Dv, p_xn, 0);
        gemm_tf32<<<gP, 128>>>(p_xn, wq, bq + l * Dv, nullptr, p_q, NTOK, Dv, Dv, Dv, Dv, 0);
        gemm_tf32<<<gP, 128>>>(p_xn, wk, bk + l * Dv, nullptr, p_k, NTOK, Dv, Dv, Dv, Dv, 0);
        gemm_tf32<<<gP, 128>>>(p_xn, wv, bv + l * Dv, nullptr, p_v, NTOK, Dv, Dv, Dv, Dv, 0);
        attn_k<<<Bv * Hv, 256>>>(p_q, p_k, p_v, rel_emb + (size_t)l * (2 * Mclip + 1) * Hv, p_att);
        gemm_tf32<<<gP, 128>>>(p_att, wo, bo + l * Dv, p_seq, p_seq, NTOK, Dv, Dv, Dv, Dv, 0);
        rmsnorm_k<<<NTOK, 256>>>(p_seq, Dv, nullptr, n2w + l * Dv, p_xn, 0);
        gemm_tf32<<<gF, 128>>>(p_xn, f1, ffb1 + l * Fv, nullptr, p_ff, NTOK, Fv, Dv, Dv, Fv, 2);
        gemm_tf32<<<gP, 128>>>(p_ff, f2, ffb2 + l * Dv, p_seq, p_seq, NTOK, Dv, Fv, Fv, Dv, 0);
    }

    // new_deter = rmsnorm(seq[:, -1] + deter, fnw)  -> out[0 : B*D)
    rmsnorm_k<<<Bv, 256>>>(p_seq + (size_t)MEMv * Dv, Sv * Dv, deter, fnw, out, 0);
    // new_mem = seq[:, 1:17]  -> out[B*D : ]
    mem_out_k<<<(Bv * MEMv * Dv + 255) / 256, 256>>>(p_seq, out + (size_t)Bv * Dv);
}

// round 7
// speedup vs baseline: 1.9205x; 1.9205x over previous
#include <cuda_runtime.h>
#include <cstdint>
#include <math.h>

// Problem constants
#define Bv    2048
#define Dv    1024
#define Hv    8
#define HDv   128
#define Fv    4096
#define Lv    2
#define Mclip 256
#define MEMv  16
#define Sv    17
#define STOv  1024
#define ACTv  32
#define HIDv  1024
#define NTOK  (Bv*Sv)       // 34816
#define TOKC  (STOv+ACTv)   // 1056
#define EPSv  1e-4f
#define SCALEv 0.08838834764831845f  // 128^-0.5

// ---------------- scratch (static device memory; no allocations) -----------
__device__ float g_tokcat[Bv*TOKC];
__device__ float g_hid[Bv*HIDv];
__device__ float g_seq[NTOK*Dv];
__device__ float g_xn [NTOK*Dv];
__device__ float g_q  [NTOK*Dv];
__device__ float g_k  [NTOK*Dv];
__device__ float g_v  [NTOK*Dv];
__device__ float g_att[NTOK*Dv];
__device__ float g_ff [(size_t)NTOK*Fv];
// converted (tf32-rounded) weights
#define W_INP1_OFF  0
#define W_INP2_OFF  (W_INP1_OFF + TOKC*HIDv)
#define W_Q_OFF     (W_INP2_OFF + HIDv*Dv)
#define W_K_OFF     (W_Q_OFF + Lv*Dv*Dv)
#define W_V_OFF     (W_K_OFF + Lv*Dv*Dv)
#define W_O_OFF     (W_V_OFF + Lv*Dv*Dv)
#define W_F1_OFF    (W_O_OFF + Lv*Dv*Dv)
#define W_F2_OFF    (W_F1_OFF + Lv*Dv*Fv)
#define W_TOTAL     (W_F2_OFF + Lv*Fv*Dv)
__device__ float g_w[W_TOTAL];

// ---------------- helpers ---------------------------------------------------
__device__ __forceinline__ float f2tf32(float x){
    uint32_t u;
    asm("cvt.rna.tf32.f32 %0, %1;" : "=r"(u) : "f"(x));
    return __uint_as_float(u);
}

__device__ __forceinline__ void mma8(float c[4], const uint32_t a[4], const uint32_t b[2]){
    asm volatile(
        "mma.sync.aligned.m16n8k8.row.col.f32.tf32.tf32.f32 "
        "{%0,%1,%2,%3}, {%4,%5,%6,%7}, {%8,%9}, {%0,%1,%2,%3};\n"
        : "+f"(c[0]), "+f"(c[1]), "+f"(c[2]), "+f"(c[3])
        : "r"(a[0]), "r"(a[1]), "r"(a[2]), "r"(a[3]), "r"(b[0]), "r"(b[1]));
}

__device__ __forceinline__ void cpa16(uint32_t s, const float* g){
    asm volatile("cp.async.cg.shared.global [%0], [%1], 16;\n" :: "r"(s), "l"(g));
}

__device__ __forceinline__ float block_reduce_sum_256(float val){
    __shared__ float sh[8];
    __shared__ float tot;
    int lane = threadIdx.x & 31, wid = threadIdx.x >> 5;
    #pragma unroll
    for (int o = 16; o; o >>= 1) val += __shfl_xor_sync(0xffffffffu, val, o);
    if (lane == 0) sh[wid] = val;
    __syncthreads();
    if (wid == 0){
        float v = (lane < 8) ? sh[lane] : 0.f;
        #pragma unroll
        for (int o = 4; o; o >>= 1) v += __shfl_xor_sync(0xffffffffu, v, o);
        if (lane == 0) tot = v;
    }
    __syncthreads();
    return tot;
}

// ---------------- weight tf32 pre-round (vectorized) ------------------------
__global__ void cvt_tf32_k(const float* __restrict__ in, float* __restrict__ out, int n4)
{
    int i = blockIdx.x * blockDim.x + threadIdx.x;
    if (i >= n4) return;
    float4 v = reinterpret_cast<const float4*>(in)[i];
    v.x = f2tf32(v.x); v.y = f2tf32(v.y); v.z = f2tf32(v.z); v.w = f2tf32(v.w);
    reinterpret_cast<float4*>(out)[i] = v;
}

// ---------------- pipelined tf32 GEMM ---------------------------------------
// C[M,N] = epi(A[M,K] @ W[K,N] + bias) (+res). Inputs already tf32-rounded.
// act: 0 = none, 1 = exact gelu + tf32-round of output.
// BM=BN=128, BK=32, 256 threads, 2-stage cp.async double buffering.
// Warp grid 2x4, warp tile 64x32 (4x4 mma tiles of 16x8).
#define BMt 128
#define BNt 128
#define BKt 32
#define GEMM_SMEM ((2*BMt*(BKt+4) + 2*BKt*(BNt+4))*4)

__global__ void __launch_bounds__(256, 2) gemm_tf32_v2(
    const float* __restrict__ A, const float* __restrict__ W,
    const float* __restrict__ bias, const float* __restrict__ res,
    float* __restrict__ C,
    int M, int N, int K, int lda, int ldc, int act)
{
    extern __shared__ float smem[];
    float (*As)[BMt][BKt+4] = reinterpret_cast<float (*)[BMt][BKt+4]>(smem);
    float (*Bs)[BKt][BNt+4] = reinterpret_cast<float (*)[BKt][BNt+4]>(smem + 2*BMt*(BKt+4));

    const int tid  = threadIdx.x;
    const int lane = tid & 31;
    const int warp = tid >> 5;
    const int wm   = (warp >> 2) * 64;     // 0,64
    const int wn   = (warp & 3) * 32;      // 0,32,64,96
    const int bm   = blockIdx.y * BMt;
    const int bn   = blockIdx.x * BNt;
    const int ar   = lane >> 2;            // 0..7
    const int ac   = lane & 3;             // 0..3

    float c[4][4][4];
    #pragma unroll
    for (int mi = 0; mi < 4; mi++)
        #pragma unroll
        for (int ni = 0; ni < 4; ni++)
            #pragma unroll
            for (int r = 0; r < 4; r++) c[mi][ni][r] = 0.f;

    // load geometry
    const int a_row = tid >> 3;            // 0..31 (4 iters stride 32)
    const int a_c4  = (tid & 7) * 4;       // 0..28
    const int b_row = tid >> 5;            // 0..7  (4 iters stride 8)
    const int b_c4  = (tid & 31) * 4;      // 0..124
    const float* Ag = A + (size_t)(bm + a_row) * lda + a_c4;
    const float* Bg = W + (size_t)b_row * N + bn + b_c4;

    uint32_t sA[2][4], sB[2][4];
    #pragma unroll
    for (int bufi = 0; bufi < 2; bufi++){
        #pragma unroll
        for (int r = 0; r < 4; r++){
            sA[bufi][r] = (uint32_t)__cvta_generic_to_shared(&As[bufi][a_row + r*32][a_c4]);
            sB[bufi][r] = (uint32_t)__cvta_generic_to_shared(&Bs[bufi][b_row + r*8][b_c4]);
        }
    }

    const int nk = K / BKt;

    // prologue: stage 0
    #pragma unroll
    for (int r = 0; r < 4; r++) cpa16(sA[0][r], Ag + (size_t)r*32*lda);
    #pragma unroll
    for (int r = 0; r < 4; r++) cpa16(sB[0][r], Bg + (size_t)r*8*N);
    asm volatile("cp.async.commit_group;\n");

    int buf = 0;
    for (int kt = 0; kt < nk; kt++){
        asm volatile("cp.async.wait_group 0;\n");
        __syncthreads();
        if (kt + 1 < nk){
            int k0 = (kt + 1) * BKt;
            int nb = buf ^ 1;
            #pragma unroll
            for (int r = 0; r < 4; r++) cpa16(sA[nb][r], Ag + (size_t)r*32*lda + k0);
            #pragma unroll
            for (int r = 0; r < 4; r++) cpa16(sB[nb][r], Bg + (size_t)(k0 + r*8)*N);
            asm volatile("cp.async.commit_group;\n");
        }

        #pragma unroll
        for (int ks = 0; ks < BKt; ks += 8){
            uint32_t a[4][4], b[4][2];
            #pragma unroll
            for (int mi = 0; mi < 4; mi++){
                int rm = wm + mi * 16;
                a[mi][0] = __float_as_uint(As[buf][rm + ar    ][ks + ac    ]);
                a[mi][1] = __float_as_uint(As[buf][rm + ar + 8][ks + ac    ]);
                a[mi][2] = __float_as_uint(As[buf][rm + ar    ][ks + ac + 4]);
                a[mi][3] = __float_as_uint(As[buf][rm + ar + 8][ks + ac + 4]);
            }
            #pragma unroll
            for (int ni = 0; ni < 4; ni++){
                int cn = wn + ni * 8 + ar;
                b[ni][0] = __float_as_uint(Bs[buf][ks + ac    ][cn]);
                b[ni][1] = __float_as_uint(Bs[buf][ks + ac + 4][cn]);
            }
            #pragma unroll
            for (int mi = 0; mi < 4; mi++)
                #pragma unroll
                for (int ni = 0; ni < 4; ni++)
                    mma8(c[mi][ni], a[mi], b[ni]);
        }
        buf ^= 1;
    }

    // epilogue
    #pragma unroll
    for (int mi = 0; mi < 4; mi++){
        #pragma unroll
        for (int ni = 0; ni < 4; ni++){
            int col = bn + wn + ni * 8 + ac * 2;
            float bx = bias ? bias[col]     : 0.f;
            float by = bias ? bias[col + 1] : 0.f;
            #pragma unroll
            for (int h = 0; h < 2; h++){
                int row = bm + wm + mi * 16 + ar + h * 8;
                float v0 = c[mi][ni][h * 2 + 0] + bx;
                float v1 = c[mi][ni][h * 2 + 1] + by;
                if (act == 1){
                    v0 = 0.5f * v0 * (1.0f + erff(v0 * 0.7071067811865475f));
                    v1 = 0.5f * v1 * (1.0f + erff(v1 * 0.7071067811865475f));
                    v0 = f2tf32(v0); v1 = f2tf32(v1);
                }
                size_t o = (size_t)row * ldc + col;
                if (res){ v0 += res[o]; v1 += res[o + 1]; }
                *reinterpret_cast<float2*>(C + o) = make_float2(v0, v1);
            }
        }
    }
}

// ---------------- rmsnorm (D=1024), optional +add, mode: 0 plain, 1 silu+round, 2 round
__global__ void rmsnorm_k(const float* __restrict__ x, int ldx,
                          const float* __restrict__ add,
                          const float* __restrict__ w,
                          float* __restrict__ y, int mode)
{
    int row = blockIdx.x;
    const float* xr = x + (size_t)row * ldx;
    float v[4]; float ss = 0.f;
    #pragma unroll
    for (int i = 0; i < 4; i++){
        int idx = threadIdx.x + i * 256;
        float t = xr[idx];
        if (add) t += add[(size_t)row * Dv + idx];
        v[i] = t; ss += t * t;
    }
    ss = block_reduce_sum_256(ss);
    float scale = rsqrtf(ss * (1.0f / Dv) + EPSv);
    #pragma unroll
    for (int i = 0; i < 4; i++){
        int idx = threadIdx.x + i * 256;
        float o = v[i] * scale * w[idx];
        if (mode == 1) o = o / (1.0f + expf(-o));   // silu
        if (mode != 0) o = f2tf32(o);
        y[(size_t)row * Dv + idx] = o;
    }
}

// ---------------- attention: one block per (b,h), S=17, HD=128 --------------
__global__ void attn_k(const float* __restrict__ Q, const float* __restrict__ K,
                       const float* __restrict__ V, const float* __restrict__ rel,
                       float* __restrict__ O)
{
    __shared__ float qs[Sv][HDv], ks[Sv][HDv], vs[Sv][HDv], sc[Sv][Sv];
    int bh = blockIdx.x;
    int b = bh >> 3, h = bh & 7;
    size_t base = (size_t)b * Sv * Dv + (size_t)h * HDv;

    for (int e = threadIdx.x; e < Sv * HDv; e += 256){
        int s = e >> 7, d = e & 127;
        size_t g = base + (size_t)s * Dv + d;
        qs[s][d] = Q[g]; ks[s][d] = K[g]; vs[s][d] = V[g];
    }
    __syncthreads();

    int lane = threadIdx.x & 31, warp = threadIdx.x >> 5;
    for (int e = warp; e < Sv * Sv; e += 8){
        int i = e / Sv, j = e % Sv;
        float p = 0.f;
        #pragma unroll
        for (int d = lane; d < HDv; d += 32) p += qs[i][d] * ks[j][d];
        #pragma unroll
        for (int o = 16; o; o >>= 1) p += __shfl_xor_sync(0xffffffffu, p, o);
        if (lane == 0){
            int r = i - j + Mclip;
            sc[i][j] = p * SCALEv + rel[r * Hv + h];
        }
    }
    __syncthreads();

    if (threadIdx.x < Sv){
        int i = threadIdx.x;
        float m = -1e30f;
        #pragma unroll
        for (int j = 0; j < Sv; j++) m = fmaxf(m, sc[i][j]);
        float s = 0.f;
        #pragma unroll
        for (int j = 0; j < Sv; j++){ float e_ = expf(sc[i][j] - m); sc[i][j] = e_; s += e_; }
        float inv = 1.0f / s;
        #pragma unroll
        for (int j = 0; j < Sv; j++) sc[i][j] *= inv;
    }
    __syncthreads();

    for (int e = threadIdx.x; e < Sv * HDv; e += 256){
        int i = e >> 7, d = e & 127;
        float acc = 0.f;
        #pragma unroll
        for (int j = 0; j < Sv; j++) acc += sc[i][j] * vs[j][d];
        O[base + (size_t)i * Dv + d] = f2tf32(acc);   // feeds Wo GEMM
    }
}

// ---------------- small data-movement kernels -------------------------------
__global__ void tokcat_k(const float* __restrict__ stoch, const float* __restrict__ action,
                         float* __restrict__ out)
{
    int idx = blockIdx.x * blockDim.x + threadIdx.x;
    if (idx >= Bv * TOKC) return;
    int b = idx / TOKC, c = idx - b * TOKC;
    float v;
    if (c < STOv) v = stoch[(size_t)b * STOv + c];
    else { float a = action[(size_t)b * ACTv + (c - STOv)]; v = a / fmaxf(fabsf(a), 1.0f); }
    out[idx] = f2tf32(v);   // feeds input MLP GEMM
}

__global__ void mem_in_k(const float* __restrict__ memory, float* __restrict__ seq)
{
    int idx = blockIdx.x * blockDim.x + threadIdx.x;
    if (idx >= Bv * MEMv * Dv) return;
    int b = idx / (MEMv * Dv);
    int r = idx - b * (MEMv * Dv);
    seq[(size_t)b * Sv * Dv + r] = memory[idx];
}

__global__ void mem_out_k(const float* __restrict__ seq, float* __restrict__ out)
{
    int idx = blockIdx.x * blockDim.x + threadIdx.x;
    if (idx >= Bv * MEMv * Dv) return;
    int b = idx / (MEMv * Dv);
    out[idx] = seq[(size_t)idx + (size_t)(b + 1) * Dv];   // seq[:, 1:17, :]
}

// ---------------- driver ----------------------------------------------------
extern "C" void kernel_launch(void* const* d_in, const int* in_sizes, int n_in,
                              void* d_out, int out_size)
{
    (void)in_sizes; (void)n_in; (void)out_size;
    const float* stoch   = (const float*)d_in[0];
    const float* deter   = (const float*)d_in[1];
    const float* action  = (const float*)d_in[2];
    const float* memory  = (const float*)d_in[3];
    const float* inp_w1  = (const float*)d_in[4];
    const float* inp_b1  = (const float*)d_in[5];
    const float* inp_nw  = (const float*)d_in[6];
    const float* inp_w2  = (const float*)d_in[7];
    const float* inp_b2  = (const float*)d_in[8];
    const float* Wq      = (const float*)d_in[9];
    const float* bq      = (const float*)d_in[10];
    const float* Wk      = (const float*)d_in[11];
    const float* bk      = (const float*)d_in[12];
    const float* Wv      = (const float*)d_in[13];
    const float* bv      = (const float*)d_in[14];
    const float* Wo      = (const float*)d_in[15];
    const float* bo      = (const float*)d_in[16];
    const float* rel_emb = (const float*)d_in[17];
    const float* n1w     = (const float*)d_in[18];
    const float* n2w     = (const float*)d_in[19];
    const float* ffw1    = (const float*)d_in[20];
    const float* ffb1    = (const float*)d_in[21];
    const float* ffw2    = (const float*)d_in[22];
    const float* ffb2    = (const float*)d_in[23];
    const float* fnw     = (const float*)d_in[24];
    float* out = (float*)d_out;

    float *p_tokcat, *p_hid, *p_seq, *p_xn, *p_q, *p_k, *p_v, *p_att, *p_ff, *p_w;
    cudaGetSymbolAddress((void**)&p_tokcat, g_tokcat);
    cudaGetSymbolAddress((void**)&p_hid, g_hid);
    cudaGetSymbolAddress((void**)&p_seq, g_seq);
    cudaGetSymbolAddress((void**)&p_xn,  g_xn);
    cudaGetSymbolAddress((void**)&p_q,   g_q);
    cudaGetSymbolAddress((void**)&p_k,   g_k);
    cudaGetSymbolAddress((void**)&p_v,   g_v);
    cudaGetSymbolAddress((void**)&p_att, g_att);
    cudaGetSymbolAddress((void**)&p_ff,  g_ff);
    cudaGetSymbolAddress((void**)&p_w,   g_w);

    cudaFuncSetAttribute(gemm_tf32_v2, cudaFuncAttributeMaxDynamicSharedMemorySize, GEMM_SMEM);

    // ---- pre-round weights to tf32 (into static scratch) ----
    auto cvt = [&](const float* src, float* dst, size_t n){
        cvt_tf32_k<<<(int)((n/4 + 255) / 256), 256>>>(src, dst, (int)(n/4));
    };
    float* w_inp1 = p_w + W_INP1_OFF;
    float* w_inp2 = p_w + W_INP2_OFF;
    float* w_q    = p_w + W_Q_OFF;
    float* w_k    = p_w + W_K_OFF;
    float* w_v    = p_w + W_V_OFF;
    float* w_o    = p_w + W_O_OFF;
    float* w_f1   = p_w + W_F1_OFF;
    float* w_f2   = p_w + W_F2_OFF;
    cvt(inp_w1, w_inp1, (size_t)TOKC*HIDv);
    cvt(inp_w2, w_inp2, (size_t)HIDv*Dv);
    cvt(Wq,     w_q,    (size_t)Lv*Dv*Dv);
    cvt(Wk,     w_k,    (size_t)Lv*Dv*Dv);
    cvt(Wv,     w_v,    (size_t)Lv*Dv*Dv);
    cvt(Wo,     w_o,    (size_t)Lv*Dv*Dv);
    cvt(ffw1,   w_f1,   (size_t)Lv*Dv*Fv);
    cvt(ffw2,   w_f2,   (size_t)Lv*Fv*Dv);

    // prep: tokcat + memory -> seq[:, :16]
    tokcat_k<<<(Bv * TOKC + 255) / 256, 256>>>(stoch, action, p_tokcat);
    mem_in_k<<<(Bv * MEMv * Dv + 255) / 256, 256>>>(memory, p_seq);

    // input MLP
    dim3 gI(Dv / BNt, Bv / BMt);           // 8 x 16
    gemm_tf32_v2<<<gI, 256, GEMM_SMEM>>>(p_tokcat, w_inp1, inp_b1, nullptr, p_hid,
                                         Bv, HIDv, TOKC, TOKC, HIDv, 0);
    rmsnorm_k<<<Bv, 256>>>(p_hid, Dv, nullptr, inp_nw, p_hid, 1);   // rmsnorm+silu+round
    gemm_tf32_v2<<<gI, 256, GEMM_SMEM>>>(p_hid, w_inp2, inp_b2, nullptr,
                                         p_seq + (size_t)MEMv * Dv,
                                         Bv, Dv, HIDv, HIDv, Sv * Dv, 0);

    dim3 gP(Dv / BNt, NTOK / BMt);         // 8 x 272
    dim3 gF(Fv / BNt, NTOK / BMt);         // 32 x 272

    for (int l = 0; l < Lv; l++){
        const float* wq = w_q + (size_t)l * Dv * Dv;
        const float* wk = w_k + (size_t)l * Dv * Dv;
        const float* wv = w_v + (size_t)l * Dv * Dv;
        const float* wo = w_o + (size_t)l * Dv * Dv;
        const float* f1 = w_f1 + (size_t)l * Dv * Fv;
        const float* f2 = w_f2 + (size_t)l * Fv * Dv;

        rmsnorm_k<<<NTOK, 256>>>(p_seq, Dv, nullptr, n1w + l * Dv, p_xn, 2);
        gemm_tf32_v2<<<gP, 256, GEMM_SMEM>>>(p_xn, wq, bq + l * Dv, nullptr, p_q, NTOK, Dv, Dv, Dv, Dv, 0);
        gemm_tf32_v2<<<gP, 256, GEMM_SMEM>>>(p_xn, wk, bk + l * Dv, nullptr, p_k, NTOK, Dv, Dv, Dv, Dv, 0);
        gemm_tf32_v2<<<gP, 256, GEMM_SMEM>>>(p_xn, wv, bv + l * Dv, nullptr, p_v, NTOK, Dv, Dv, Dv, Dv, 0);
        attn_k<<<Bv * Hv, 256>>>(p_q, p_k, p_v, rel_emb + (size_t)l * (2 * Mclip + 1) * Hv, p_att);
        gemm_tf32_v2<<<gP, 256, GEMM_SMEM>>>(p_att, wo, bo + l * Dv, p_seq, p_seq, NTOK, Dv, Dv, Dv, Dv, 0);
        rmsnorm_k<<<NTOK, 256>>>(p_seq, Dv, nullptr, n2w + l * Dv, p_xn, 2);
        gemm_tf32_v2<<<gF, 256, GEMM_SMEM>>>(p_xn, f1, ffb1 + l * Fv, nullptr, p_ff, NTOK, Fv, Dv, Dv, Fv, 1);
        gemm_tf32_v2<<<gP, 256, GEMM_SMEM>>>(p_ff, f2, ffb2 + l * Dv, p_seq, p_seq, NTOK, Dv, Fv, Fv, Dv, 0);
    }

    // new_deter = rmsnorm(seq[:, -1] + deter, fnw)  -> out[0 : B*D)
    rmsnorm_k<<<Bv, 256>>>(p_seq + (size_t)MEMv * Dv, Sv * Dv, deter, fnw, out, 0);
    // new_mem = seq[:, 1:17]  -> out[B*D : ]
    mem_out_k<<<(Bv * MEMv * Dv + 255) / 256, 256>>>(p_seq, out + (size_t)Bv * Dv);
}

// round 9
// speedup vs baseline: 2.0166x; 1.0500x over previous
#include <cuda_runtime.h>
#include <cstdint>
#include <math.h>

// Problem constants
#define Bv    2048
#define Dv    1024
#define Hv    8
#define HDv   128
#define Fv    4096
#define Lv    2
#define Mclip 256
#define MEMv  16
#define Sv    17
#define STOv  1024
#define ACTv  32
#define HIDv  1024
#define NTOK  (Bv*Sv)       // 34816
#define TOKC  (STOv+ACTv)   // 1056
#define QKVN  3072
#define EPSv  1e-4f
#define SCALEv 0.08838834764831845f  // 128^-0.5

// ---------------- scratch (static device memory; no allocations) -----------
__device__ float g_tokcat[Bv*TOKC];
__device__ float g_hid[Bv*HIDv];
__device__ float g_seq[NTOK*Dv];
__device__ float g_xn [NTOK*Dv];
__device__ float g_qkv[(size_t)NTOK*QKVN];
__device__ float g_att[NTOK*Dv];
__device__ float g_ff [(size_t)NTOK*Fv];
// converted (tf32-rounded) weights, [K,N] N-major
#define W_INP1_OFF  0
#define W_INP2_OFF  (W_INP1_OFF + TOKC*HIDv)
#define W_QKV_OFF   (W_INP2_OFF + HIDv*Dv)
#define W_O_OFF     (W_QKV_OFF + Lv*Dv*QKVN)
#define W_F1_OFF    (W_O_OFF + Lv*Dv*Dv)
#define W_F2_OFF    (W_F1_OFF + Lv*Dv*Fv)
#define W_TOTAL     (W_F2_OFF + Lv*Fv*Dv)
__device__ float g_w[W_TOTAL];
__device__ float g_bqkv[Lv*QKVN];

// ---------------- helpers ---------------------------------------------------
__device__ __forceinline__ float f2tf32(float x){
    uint32_t u;
    asm("cvt.rna.tf32.f32 %0, %1;" : "=r"(u) : "f"(x));
    return __uint_as_float(u);
}

__device__ __forceinline__ void mma8(float c[4], const uint32_t a[4], const uint32_t b[2]){
    asm volatile(
        "mma.sync.aligned.m16n8k8.row.col.f32.tf32.tf32.f32 "
        "{%0,%1,%2,%3}, {%4,%5,%6,%7}, {%8,%9}, {%0,%1,%2,%3};\n"
        : "+f"(c[0]), "+f"(c[1]), "+f"(c[2]), "+f"(c[3])
        : "r"(a[0]), "r"(a[1]), "r"(a[2]), "r"(a[3]), "r"(b[0]), "r"(b[1]));
}

__device__ __forceinline__ void cpa16(uint32_t s, const float* g){
    asm volatile("cp.async.cg.shared.global [%0], [%1], 16;\n" :: "r"(s), "l"(g));
}
#define CP_COMMIT() asm volatile("cp.async.commit_group;\n" ::: "memory")
#define CP_WAIT(n)  asm volatile("cp.async.wait_group %0;\n" :: "n"(n) : "memory")

__device__ __forceinline__ float block_reduce_sum_256(float val){
    __shared__ float sh[8];
    __shared__ float tot;
    int lane = threadIdx.x & 31, wid = threadIdx.x >> 5;
    #pragma unroll
    for (int o = 16; o; o >>= 1) val += __shfl_xor_sync(0xffffffffu, val, o);
    if (lane == 0) sh[wid] = val;
    __syncthreads();
    if (wid == 0){
        float v = (lane < 8) ? sh[lane] : 0.f;
        #pragma unroll
        for (int o = 4; o; o >>= 1) v += __shfl_xor_sync(0xffffffffu, v, o);
        if (lane == 0) tot = v;
    }
    __syncthreads();
    return tot;
}

// ---------------- weight conversion / packing --------------------------------
__global__ void cvt_tf32_k(const float* __restrict__ in, float* __restrict__ out, int n4)
{
    int i = blockIdx.x * blockDim.x + threadIdx.x;
    if (i >= n4) return;
    float4 v = reinterpret_cast<const float4*>(in)[i];
    v.x = f2tf32(v.x); v.y = f2tf32(v.y); v.z = f2tf32(v.z); v.w = f2tf32(v.w);
    reinterpret_cast<float4*>(out)[i] = v;
}

// pack Wq|Wk|Wv -> [L][K=1024][3072] N-major, tf32-rounded
__global__ void packw_qkv_k(const float* __restrict__ Wq, const float* __restrict__ Wk,
                            const float* __restrict__ Wv, float* __restrict__ out)
{
    size_t idx = (size_t)blockIdx.x * blockDim.x + threadIdx.x;
    if (idx >= (size_t)Lv * Dv * QKVN) return;
    size_t lk = idx / QKVN;          // l*Dv + k
    int c = (int)(idx % QKVN);
    const float* src = (c < Dv) ? Wq : (c < 2*Dv) ? Wk : Wv;
    int cc = c & (Dv - 1);
    out[idx] = f2tf32(src[lk * Dv + cc]);
}

__global__ void packb_qkv_k(const float* __restrict__ bq, const float* __restrict__ bk,
                            const float* __restrict__ bv, float* __restrict__ out)
{
    int i = blockIdx.x * blockDim.x + threadIdx.x;
    if (i >= Lv * QKVN) return;
    int l = i / QKVN, c = i % QKVN;
    const float* src = (c < Dv) ? bq : (c < 2*Dv) ? bk : bv;
    out[i] = src[l * Dv + (c & (Dv - 1))];
}

// ---------------- 3-stage pipelined tf32 GEMM --------------------------------
// C[M,N] = epi(A[M,K] @ W[K,N] + bias) (+res). Inputs already tf32-rounded.
// act: 0 = none, 1 = exact gelu + tf32-round of output.
// BM=BN=128, BK=32, 256 threads, 3-stage cp.async, wait_group 1.
#define BMt 128
#define BNt 128
#define BKt 32
#define ASZ (BMt*(BKt+4))        // 4608 floats
#define BSZ (BKt*(BNt+4))        // 4224 floats
#define STGF (ASZ+BSZ)           // 8832 floats
#define NSTG 3
#define GEMM_SMEM (NSTG*STGF*4)  // 105984 B

__global__ void __launch_bounds__(256, 2) gemm_tf32_v3(
    const float* __restrict__ A, const float* __restrict__ W,
    const float* __restrict__ bias, const float* __restrict__ res,
    float* __restrict__ C,
    int M, int N, int K, int lda, int ldc, int act)
{
    extern __shared__ float sm[];

    const int tid  = threadIdx.x;
    const int lane = tid & 31;
    const int warp = tid >> 5;
    const int wm   = (warp >> 2) * 64;     // 0,64
    const int wn   = (warp & 3) * 32;      // 0,32,64,96
    const int bm   = blockIdx.y * BMt;
    const int bn   = blockIdx.x * BNt;
    const int ar   = lane >> 2;            // 0..7
    const int ac   = lane & 3;             // 0..3

    float c[4][4][4];
    #pragma unroll
    for (int mi = 0; mi < 4; mi++)
        #pragma unroll
        for (int ni = 0; ni < 4; ni++)
            #pragma unroll
            for (int r = 0; r < 4; r++) c[mi][ni][r] = 0.f;

    // load geometry (16B chunks)
    const int a_row = tid >> 3;            // 0..31 (4 iters stride 32)
    const int a_c4  = (tid & 7) * 4;       // 0..28
    const int b_row = tid >> 5;            // 0..7  (4 iters stride 8)
    const int b_c4  = (tid & 31) * 4;      // 0..124
    const float* Ag = A + (size_t)(bm + a_row) * lda + a_c4;
    const float* Bg = W + (size_t)b_row * N + bn + b_c4;

    uint32_t smem_u = (uint32_t)__cvta_generic_to_shared(sm);
    uint32_t aoff[4], boff[4];
    #pragma unroll
    for (int r = 0; r < 4; r++){
        aoff[r] = ((a_row + r*32) * (BKt+4) + a_c4) * 4;
        boff[r] = (ASZ + (b_row + r*8) * (BNt+4) + b_c4) * 4;
    }

    const int nk = K / BKt;

    // prologue: tiles 0,1 into stages 0,1
    #pragma unroll
    for (int s = 0; s < 2; s++){
        uint32_t sb = smem_u + s * (STGF*4);
        int k0 = s * BKt;
        #pragma unroll
        for (int r = 0; r < 4; r++) cpa16(sb + aoff[r], Ag + (size_t)r*32*lda + k0);
        #pragma unroll
        for (int r = 0; r < 4; r++) cpa16(sb + boff[r], Bg + (size_t)(k0 + r*8)*N);
        CP_COMMIT();
    }

    int s = 0;
    for (int kt = 0; kt < nk; kt++){
        if (kt + 1 < nk) CP_WAIT(1); else CP_WAIT(0);
        __syncthreads();

        int pf = kt + 2;
        if (pf < nk){
            int ps = pf % NSTG;
            uint32_t sb = smem_u + ps * (STGF*4);
            int k0 = pf * BKt;
            #pragma unroll
            for (int r = 0; r < 4; r++) cpa16(sb + aoff[r], Ag + (size_t)r*32*lda + k0);
            #pragma unroll
            for (int r = 0; r < 4; r++) cpa16(sb + boff[r], Bg + (size_t)(k0 + r*8)*N);
            CP_COMMIT();
        }

        const float* As = sm + s * STGF;               // [128][36]
        const float* Bs = sm + s * STGF + ASZ;         // [32][132]
        #pragma unroll
        for (int ks = 0; ks < BKt; ks += 8){
            uint32_t a[4][4], b[4][2];
            #pragma unroll
            for (int mi = 0; mi < 4; mi++){
                int rm = wm + mi * 16;
                a[mi][0] = __float_as_uint(As[(rm + ar    )*(BKt+4) + ks + ac    ]);
                a[mi][1] = __float_as_uint(As[(rm + ar + 8)*(BKt+4) + ks + ac    ]);
                a[mi][2] = __float_as_uint(As[(rm + ar    )*(BKt+4) + ks + ac + 4]);
                a[mi][3] = __float_as_uint(As[(rm + ar + 8)*(BKt+4) + ks + ac + 4]);
            }
            #pragma unroll
            for (int ni = 0; ni < 4; ni++){
                int cn = wn + ni * 8 + ar;
                b[ni][0] = __float_as_uint(Bs[(ks + ac    )*(BNt+4) + cn]);
                b[ni][1] = __float_as_uint(Bs[(ks + ac + 4)*(BNt+4) + cn]);
            }
            #pragma unroll
            for (int mi = 0; mi < 4; mi++)
                #pragma unroll
                for (int ni = 0; ni < 4; ni++)
                    mma8(c[mi][ni], a[mi], b[ni]);
        }
        s++; if (s == NSTG) s = 0;
    }

    // epilogue
    #pragma unroll
    for (int mi = 0; mi < 4; mi++){
        #pragma unroll
        for (int ni = 0; ni < 4; ni++){
            int col = bn + wn + ni * 8 + ac * 2;
            float bx = bias ? bias[col]     : 0.f;
            float by = bias ? bias[col + 1] : 0.f;
            #pragma unroll
            for (int h = 0; h < 2; h++){
                int row = bm + wm + mi * 16 + ar + h * 8;
                float v0 = c[mi][ni][h * 2 + 0] + bx;
                float v1 = c[mi][ni][h * 2 + 1] + by;
                if (act == 1){
                    v0 = 0.5f * v0 * (1.0f + erff(v0 * 0.7071067811865475f));
                    v1 = 0.5f * v1 * (1.0f + erff(v1 * 0.7071067811865475f));
                    v0 = f2tf32(v0); v1 = f2tf32(v1);
                }
                size_t o = (size_t)row * ldc + col;
                if (res){ v0 += res[o]; v1 += res[o + 1]; }
                *reinterpret_cast<float2*>(C + o) = make_float2(v0, v1);
            }
        }
    }
}

// ---------------- rmsnorm (D=1024) float4; mode: 0 plain, 1 silu+round, 2 round
__global__ void rmsnorm_k(const float* __restrict__ x, int ldx,
                          const float* __restrict__ add,
                          const float* __restrict__ w,
                          float* __restrict__ y, int mode)
{
    int row = blockIdx.x;
    float4 v = reinterpret_cast<const float4*>(x + (size_t)row * ldx)[threadIdx.x];
    if (add){
        float4 a = reinterpret_cast<const float4*>(add + (size_t)row * Dv)[threadIdx.x];
        v.x += a.x; v.y += a.y; v.z += a.z; v.w += a.w;
    }
    float ss = v.x*v.x + v.y*v.y + v.z*v.z + v.w*v.w;
    ss = block_reduce_sum_256(ss);
    float scale = rsqrtf(ss * (1.0f / Dv) + EPSv);
    float4 wv = reinterpret_cast<const float4*>(w)[threadIdx.x];
    v.x *= scale * wv.x; v.y *= scale * wv.y; v.z *= scale * wv.z; v.w *= scale * wv.w;
    if (mode == 1){
        v.x = v.x / (1.0f + expf(-v.x)); v.y = v.y / (1.0f + expf(-v.y));
        v.z = v.z / (1.0f + expf(-v.z)); v.w = v.w / (1.0f + expf(-v.w));
    }
    if (mode != 0){
        v.x = f2tf32(v.x); v.y = f2tf32(v.y); v.z = f2tf32(v.z); v.w = f2tf32(v.w);
    }
    reinterpret_cast<float4*>(y + (size_t)row * Dv)[threadIdx.x] = v;
}

// ---------------- attention on packed QKV: one block per (b,h) ---------------
__global__ void attn_k(const float* __restrict__ QKV, const float* __restrict__ rel,
                       float* __restrict__ O)
{
    __shared__ float qs[Sv][HDv], ks[Sv][HDv], vs[Sv][HDv], sc[Sv][Sv];
    int bh = blockIdx.x;
    int b = bh >> 3, h = bh & 7;
    size_t rowbase = (size_t)b * Sv * QKVN + (size_t)h * HDv;

    for (int e = threadIdx.x; e < Sv * 32; e += 256){
        int sI = e >> 5, d4 = e & 31;
        const float* p = QKV + rowbase + (size_t)sI * QKVN + d4 * 4;
        float4 q4 = *reinterpret_cast<const float4*>(p);
        float4 k4 = *reinterpret_cast<const float4*>(p + Dv);
        float4 v4 = *reinterpret_cast<const float4*>(p + 2*Dv);
        *reinterpret_cast<float4*>(&qs[sI][d4*4]) = q4;
        *reinterpret_cast<float4*>(&ks[sI][d4*4]) = k4;
        *reinterpret_cast<float4*>(&vs[sI][d4*4]) = v4;
    }
    __syncthreads();

    int lane = threadIdx.x & 31, warp = threadIdx.x >> 5;
    for (int e = warp; e < Sv * Sv; e += 8){
        int i = e / Sv, j = e % Sv;
        float p = 0.f;
        #pragma unroll
        for (int d = lane; d < HDv; d += 32) p += qs[i][d] * ks[j][d];
        #pragma unroll
        for (int o = 16; o; o >>= 1) p += __shfl_xor_sync(0xffffffffu, p, o);
        if (lane == 0){
            int r = i - j + Mclip;
            sc[i][j] = p * SCALEv + rel[r * Hv + h];
        }
    }
    __syncthreads();

    if (threadIdx.x < Sv){
        int i = threadIdx.x;
        float m = -1e30f;
        #pragma unroll
        for (int j = 0; j < Sv; j++) m = fmaxf(m, sc[i][j]);
        float s = 0.f;
        #pragma unroll
        for (int j = 0; j < Sv; j++){ float e_ = expf(sc[i][j] - m); sc[i][j] = e_; s += e_; }
        float inv = 1.0f / s;
        #pragma unroll
        for (int j = 0; j < Sv; j++) sc[i][j] *= inv;
    }
    __syncthreads();

    size_t obase = (size_t)b * Sv * Dv + (size_t)h * HDv;
    for (int e = threadIdx.x; e < Sv * HDv; e += 256){
        int i = e >> 7, d = e & 127;
        float acc = 0.f;
        #pragma unroll
        for (int j = 0; j < Sv; j++) acc += sc[i][j] * vs[j][d];
        O[obase + (size_t)i * Dv + d] = f2tf32(acc);   // feeds Wo GEMM
    }
}

// ---------------- small data-movement kernels -------------------------------
__global__ void tokcat_k(const float* __restrict__ stoch, const float* __restrict__ action,
                         float* __restrict__ out)
{
    int idx = blockIdx.x * blockDim.x + threadIdx.x;
    if (idx >= Bv * TOKC) return;
    int b = idx / TOKC, c = idx - b * TOKC;
    float v;
    if (c < STOv) v = stoch[(size_t)b * STOv + c];
    else { float a = action[(size_t)b * ACTv + (c - STOv)]; v = a / fmaxf(fabsf(a), 1.0f); }
    out[idx] = f2tf32(v);
}

__global__ void mem_in_k(const float* __restrict__ memory, float* __restrict__ seq)
{
    int idx = blockIdx.x * blockDim.x + threadIdx.x;
    if (idx >= Bv * MEMv * Dv / 4) return;
    int b = idx / (MEMv * Dv / 4);
    int r = idx - b * (MEMv * Dv / 4);
    reinterpret_cast<float4*>(seq + (size_t)b * Sv * Dv)[r] =
        reinterpret_cast<const float4*>(memory)[idx];
}

__global__ void mem_out_k(const float* __restrict__ seq, float* __restrict__ out)
{
    int idx = blockIdx.x * blockDim.x + threadIdx.x;
    if (idx >= Bv * MEMv * Dv / 4) return;
    int b = idx / (MEMv * Dv / 4);
    reinterpret_cast<float4*>(out)[idx] =
        reinterpret_cast<const float4*>(seq + (size_t)(b + 1) * Dv)[idx];  // seq[:,1:17,:]
}

// ---------------- driver ----------------------------------------------------
extern "C" void kernel_launch(void* const* d_in, const int* in_sizes, int n_in,
                              void* d_out, int out_size)
{
    (void)in_sizes; (void)n_in; (void)out_size;
    const float* stoch   = (const float*)d_in[0];
    const float* deter   = (const float*)d_in[1];
    const float* action  = (const float*)d_in[2];
    const float* memory  = (const float*)d_in[3];
    const float* inp_w1  = (const float*)d_in[4];
    const float* inp_b1  = (const float*)d_in[5];
    const float* inp_nw  = (const float*)d_in[6];
    const float* inp_w2  = (const float*)d_in[7];
    const float* inp_b2  = (const float*)d_in[8];
    const float* Wq      = (const float*)d_in[9];
    const float* bq      = (const float*)d_in[10];
    const float* Wk      = (const float*)d_in[11];
    const float* bk      = (const float*)d_in[12];
    const float* Wv      = (const float*)d_in[13];
    const float* bv      = (const float*)d_in[14];
    const float* Wo      = (const float*)d_in[15];
    const float* bo      = (const float*)d_in[16];
    const float* rel_emb = (const float*)d_in[17];
    const float* n1w     = (const float*)d_in[18];
    const float* n2w     = (const float*)d_in[19];
    const float* ffw1    = (const float*)d_in[20];
    const float* ffb1    = (const float*)d_in[21];
    const float* ffw2    = (const float*)d_in[22];
    const float* ffb2    = (const float*)d_in[23];
    const float* fnw     = (const float*)d_in[24];
    float* out = (float*)d_out;

    float *p_tokcat, *p_hid, *p_seq, *p_xn, *p_qkv, *p_att, *p_ff, *p_w, *p_bqkv;
    cudaGetSymbolAddress((void**)&p_tokcat, g_tokcat);
    cudaGetSymbolAddress((void**)&p_hid, g_hid);
    cudaGetSymbolAddress((void**)&p_seq, g_seq);
    cudaGetSymbolAddress((void**)&p_xn,  g_xn);
    cudaGetSymbolAddress((void**)&p_qkv, g_qkv);
    cudaGetSymbolAddress((void**)&p_att, g_att);
    cudaGetSymbolAddress((void**)&p_ff,  g_ff);
    cudaGetSymbolAddress((void**)&p_w,   g_w);
    cudaGetSymbolAddress((void**)&p_bqkv, g_bqkv);

    cudaFuncSetAttribute(gemm_tf32_v3, cudaFuncAttributeMaxDynamicSharedMemorySize, GEMM_SMEM);

    // ---- convert / pack weights (tf32-rounded) ----
    auto cvt = [&](const float* src, float* dst, size_t n){
        cvt_tf32_k<<<(int)((n/4 + 255) / 256), 256>>>(src, dst, (int)(n/4));
    };
    float* w_inp1 = p_w + W_INP1_OFF;
    float* w_inp2 = p_w + W_INP2_OFF;
    float* w_qkv  = p_w + W_QKV_OFF;
    float* w_o    = p_w + W_O_OFF;
    float* w_f1   = p_w + W_F1_OFF;
    float* w_f2   = p_w + W_F2_OFF;
    cvt(inp_w1, w_inp1, (size_t)TOKC*HIDv);
    cvt(inp_w2, w_inp2, (size_t)HIDv*Dv);
    cvt(Wo,     w_o,    (size_t)Lv*Dv*Dv);
    cvt(ffw1,   w_f1,   (size_t)Lv*Dv*Fv);
    cvt(ffw2,   w_f2,   (size_t)Lv*Fv*Dv);
    {
        size_t n = (size_t)Lv * Dv * QKVN;
        packw_qkv_k<<<(int)((n + 255) / 256), 256>>>(Wq, Wk, Wv, w_qkv);
        packb_qkv_k<<<(Lv * QKVN + 255) / 256, 256>>>(bq, bk, bv, p_bqkv);
    }

    // prep: tokcat + memory -> seq[:, :16]
    tokcat_k<<<(Bv * TOKC + 255) / 256, 256>>>(stoch, action, p_tokcat);
    mem_in_k<<<(Bv * MEMv * Dv / 4 + 255) / 256, 256>>>(memory, p_seq);

    // input MLP
    dim3 gI(Dv / BNt, Bv / BMt);           // 8 x 16
    gemm_tf32_v3<<<gI, 256, GEMM_SMEM>>>(p_tokcat, w_inp1, inp_b1, nullptr, p_hid,
                                         Bv, HIDv, TOKC, TOKC, HIDv, 0);
    rmsnorm_k<<<Bv, 256>>>(p_hid, Dv, nullptr, inp_nw, p_hid, 1);   // rmsnorm+silu+round
    gemm_tf32_v3<<<gI, 256, GEMM_SMEM>>>(p_hid, w_inp2, inp_b2, nullptr,
                                         p_seq + (size_t)MEMv * Dv,
                                         Bv, Dv, HIDv, HIDv, Sv * Dv, 0);

    dim3 gQ(QKVN / BNt, NTOK / BMt);       // 24 x 272
    dim3 gP(Dv / BNt, NTOK / BMt);         // 8 x 272
    dim3 gF(Fv / BNt, NTOK / BMt);         // 32 x 272

    for (int l = 0; l < Lv; l++){
        const float* wqkv = w_qkv + (size_t)l * Dv * QKVN;
        const float* wo   = w_o   + (size_t)l * Dv * Dv;
        const float* f1   = w_f1  + (size_t)l * Dv * Fv;
        const float* f2   = w_f2  + (size_t)l * Fv * Dv;

        rmsnorm_k<<<NTOK, 256>>>(p_seq, Dv, nullptr, n1w + l * Dv, p_xn, 2);
        gemm_tf32_v3<<<gQ, 256, GEMM_SMEM>>>(p_xn, wqkv, p_bqkv + l * QKVN, nullptr, p_qkv,
                                             NTOK, QKVN, Dv, Dv, QKVN, 0);
        attn_k<<<Bv * Hv, 256>>>(p_qkv, rel_emb + (size_t)l * (2 * Mclip + 1) * Hv, p_att);
        gemm_tf32_v3<<<gP, 256, GEMM_SMEM>>>(p_att, wo, bo + l * Dv, p_seq, p_seq,
                                             NTOK, Dv, Dv, Dv, Dv, 0);
        rmsnorm_k<<<NTOK, 256>>>(p_seq, Dv, nullptr, n2w + l * Dv, p_xn, 2);
        gemm_tf32_v3<<<gF, 256, GEMM_SMEM>>>(p_xn, f1, ffb1 + l * Fv, nullptr, p_ff,
                                             NTOK, Fv, Dv, Dv, Fv, 1);
        gemm_tf32_v3<<<gP, 256, GEMM_SMEM>>>(p_ff, f2, ffb2 + l * Dv, p_seq, p_seq,
                                             NTOK, Dv, Fv, Fv, Dv, 0);
    }

    // new_deter = rmsnorm(seq[:, -1] + deter, fnw)  -> out[0 : B*D)
    rmsnorm_k<<<Bv, 256>>>(p_seq + (size_t)MEMv * Dv, Sv * Dv, deter, fnw, out, 0);
    // new_mem = seq[:, 1:17]  -> out[B*D : ]
    mem_out_k<<<(Bv * MEMv * Dv / 4 + 255) / 256, 256>>>(p_seq, out + (size_t)Bv * Dv);
}

// round 10
// speedup vs baseline: 3.9798x; 1.9736x over previous
#include <cuda_runtime.h>
#include <cuda_fp16.h>
#include <cstdint>
#include <math.h>

// Problem constants
#define Bv    2048
#define Dv    1024
#define Hv    8
#define HDv   128
#define Fv    4096
#define Lv    2
#define Mclip 256
#define MEMv  16
#define Sv    17
#define STOv  1024
#define ACTv  32
#define HIDv  1024
#define NTOK  (Bv*Sv)       // 34816
#define TOKC  (STOv+ACTv)   // 1056
#define TOKCP 1088          // padded to multiple of 64
#define QKVN  3072
#define EPSv  1e-4f
#define SCALEv 0.08838834764831845f  // 128^-0.5

// ---------------- scratch (static device memory; no allocations) -----------
__device__ __half g_tokcat[Bv*TOKCP];
__device__ float  g_hid [Bv*HIDv];
__device__ __half g_hidh[Bv*HIDv];
__device__ float  g_seq [NTOK*Dv];
__device__ __half g_xn  [NTOK*Dv];
__device__ __half g_qkv [(size_t)NTOK*QKVN];
__device__ __half g_att [NTOK*Dv];
__device__ __half g_ff  [(size_t)NTOK*Fv];
// fp16 weights, [N][K] K-major (transposed)
#define W_INP1_OFF  0
#define W_INP2_OFF  (W_INP1_OFF + (size_t)HIDv*TOKCP)
#define W_QKV_OFF   (W_INP2_OFF + (size_t)Dv*HIDv)
#define W_O_OFF     (W_QKV_OFF + (size_t)Lv*QKVN*Dv)
#define W_F1_OFF    (W_O_OFF + (size_t)Lv*Dv*Dv)
#define W_F2_OFF    (W_F1_OFF + (size_t)Lv*Fv*Dv)
#define W_TOTAL     (W_F2_OFF + (size_t)Lv*Dv*Fv)
__device__ __half g_w[W_TOTAL];
__device__ float g_bqkv[Lv*QKVN];

// ---------------- helpers ---------------------------------------------------
__device__ __forceinline__ void mma16(float c[4], const uint32_t a[4], const uint32_t b[2]){
    asm volatile(
        "mma.sync.aligned.m16n8k16.row.col.f32.f16.f16.f32 "
        "{%0,%1,%2,%3}, {%4,%5,%6,%7}, {%8,%9}, {%0,%1,%2,%3};\n"
        : "+f"(c[0]), "+f"(c[1]), "+f"(c[2]), "+f"(c[3])
        : "r"(a[0]), "r"(a[1]), "r"(a[2]), "r"(a[3]), "r"(b[0]), "r"(b[1]));
}

__device__ __forceinline__ void cpa16(uint32_t s, const void* g){
    asm volatile("cp.async.cg.shared.global [%0], [%1], 16;\n" :: "r"(s), "l"(g));
}
#define CP_COMMIT() asm volatile("cp.async.commit_group;\n" ::: "memory")
#define CP_WAIT(n)  asm volatile("cp.async.wait_group %0;\n" :: "n"(n) : "memory")

__device__ __forceinline__ float block_reduce_sum_256(float val){
    __shared__ float sh[8];
    __shared__ float tot;
    int lane = threadIdx.x & 31, wid = threadIdx.x >> 5;
    #pragma unroll
    for (int o = 16; o; o >>= 1) val += __shfl_xor_sync(0xffffffffu, val, o);
    if (lane == 0) sh[wid] = val;
    __syncthreads();
    if (wid == 0){
        float v = (lane < 8) ? sh[lane] : 0.f;
        #pragma unroll
        for (int o = 4; o; o >>= 1) v += __shfl_xor_sync(0xffffffffu, v, o);
        if (lane == 0) tot = v;
    }
    __syncthreads();
    return tot;
}

// ---------------- weight convert: [K,N] fp32 -> [N,Kpad] fp16 ---------------
__global__ void wcvt_h(const float* __restrict__ in, __half* __restrict__ out,
                       int Kin, int Kpad, int N)
{
    __shared__ float t[32][33];
    int kb = blockIdx.y * 32, nb = blockIdx.x * 32;
    int tx = threadIdx.x, ty = threadIdx.y;   // block (32,8)
    #pragma unroll
    for (int j = 0; j < 4; j++){
        int k = kb + ty + j*8;
        t[ty + j*8][tx] = (k < Kin) ? in[(size_t)k * N + nb + tx] : 0.f;
    }
    __syncthreads();
    #pragma unroll
    for (int j = 0; j < 4; j++)
        out[(size_t)(nb + ty + j*8) * Kpad + kb + tx] = __float2half_rn(t[tx][ty + j*8]);
}

__global__ void packb_qkv_k(const float* __restrict__ bq, const float* __restrict__ bk,
                            const float* __restrict__ bv, float* __restrict__ out)
{
    int i = blockIdx.x * blockDim.x + threadIdx.x;
    if (i >= Lv * QKVN) return;
    int l = i / QKVN, c = i % QKVN;
    const float* src = (c < Dv) ? bq : (c < 2*Dv) ? bk : bv;
    out[i] = src[l * Dv + (c & (Dv - 1))];
}

// ---------------- fp16 GEMM, fp32 accumulate --------------------------------
// C[M,N] = epi(A[M,K] @ Wt[N,K]^T + bias). A,Wt fp16. acc fp32.
// act: 0 none, 1 exact gelu. outHalf: write __half (no res) or float (+res).
// BM=BN=128, BK=64 halves. 256 threads, 8 warps (2x4), warp tile 64x32.
// 3-stage cp.async, wait_group 1.
#define BMh 128
#define BNh 128
#define BKh 64
#define LDAh 72                    // padded row stride in halves
#define ASZh (BMh*LDAh)            // 9216 halves
#define STGH (2*ASZh)              // A+B per stage, halves
#define NSTG 3
#define GEMM_SMEMH (NSTG*STGH*2)   // 110592 B

__global__ void __launch_bounds__(256, 2) gemm_h(
    const __half* __restrict__ A, const __half* __restrict__ Wt,
    const float* __restrict__ bias, const float* __restrict__ res,
    float* __restrict__ C, __half* __restrict__ Ch,
    int M, int N, int K, int lda, int ldc, int act, int outHalf)
{
    extern __shared__ __half smh[];

    const int tid  = threadIdx.x;
    const int lane = tid & 31;
    const int warp = tid >> 5;
    const int wm   = (warp >> 2) * 64;     // 0,64
    const int wn   = (warp & 3) * 32;      // 0,32,64,96
    const int bm   = blockIdx.y * BMh;
    const int bn   = blockIdx.x * BNh;
    const int g    = lane >> 2;            // 0..7
    const int tg   = lane & 3;             // 0..3

    float c[4][4][4];
    #pragma unroll
    for (int mi = 0; mi < 4; mi++)
        #pragma unroll
        for (int ni = 0; ni < 4; ni++)
            #pragma unroll
            for (int r = 0; r < 4; r++) c[mi][ni][r] = 0.f;

    // load geometry: 16B chunks (8 halves). Tile rows of 64 halves = 8 chunks.
    // 128 rows * 8 chunks = 1024 chunks; 256 threads -> 4 each for A, 4 for B.
    const int c_row = tid >> 3;            // 0..31, stride 32 over 4 iters
    const int c_c8  = (tid & 7) * 8;       // half offset within row
    const __half* Ag = A  + (size_t)(bm + c_row) * lda + c_c8;
    const __half* Bg = Wt + (size_t)(bn + c_row) * K   + c_c8;

    uint32_t smem_u = (uint32_t)__cvta_generic_to_shared(smh);
    uint32_t aoff[4], boff[4];
    #pragma unroll
    for (int r = 0; r < 4; r++){
        aoff[r] = ((c_row + r*32) * LDAh + c_c8) * 2;
        boff[r] = aoff[r] + ASZh*2;
    }

    const int nk = K / BKh;

    // prologue: tiles 0,1 into stages 0,1
    #pragma unroll
    for (int s = 0; s < 2; s++){
        uint32_t sb = smem_u + s * (STGH*2);
        int k0 = s * BKh;
        #pragma unroll
        for (int r = 0; r < 4; r++) cpa16(sb + aoff[r], Ag + (size_t)r*32*lda + k0);
        #pragma unroll
        for (int r = 0; r < 4; r++) cpa16(sb + boff[r], Bg + (size_t)r*32*K + k0);
        CP_COMMIT();
    }

    int s = 0;
    for (int kt = 0; kt < nk; kt++){
        if (kt + 1 < nk) CP_WAIT(1); else CP_WAIT(0);
        __syncthreads();

        int pf = kt + 2;
        if (pf < nk){
            int ps = pf % NSTG;
            uint32_t sb = smem_u + ps * (STGH*2);
            int k0 = pf * BKh;
            #pragma unroll
            for (int r = 0; r < 4; r++) cpa16(sb + aoff[r], Ag + (size_t)r*32*lda + k0);
            #pragma unroll
            for (int r = 0; r < 4; r++) cpa16(sb + boff[r], Bg + (size_t)r*32*K + k0);
            CP_COMMIT();
        }

        const __half* As = smh + s * STGH;
        const __half* Bs = As + ASZh;
        #pragma unroll
        for (int ks = 0; ks < BKh; ks += 16){
            uint32_t a[4][4], b[4][2];
            #pragma unroll
            for (int mi = 0; mi < 4; mi++){
                int rm = wm + mi * 16 + g;
                const __half* p0 = As + rm * LDAh + ks + 2*tg;
                a[mi][0] = *reinterpret_cast<const uint32_t*>(p0);
                a[mi][1] = *reinterpret_cast<const uint32_t*>(p0 + 8*LDAh);
                a[mi][2] = *reinterpret_cast<const uint32_t*>(p0 + 8);
                a[mi][3] = *reinterpret_cast<const uint32_t*>(p0 + 8*LDAh + 8);
            }
            #pragma unroll
            for (int ni = 0; ni < 4; ni++){
                int cn = wn + ni * 8 + g;
                const __half* p0 = Bs + cn * LDAh + ks + 2*tg;
                b[ni][0] = *reinterpret_cast<const uint32_t*>(p0);
                b[ni][1] = *reinterpret_cast<const uint32_t*>(p0 + 8);
            }
            #pragma unroll
            for (int mi = 0; mi < 4; mi++)
                #pragma unroll
                for (int ni = 0; ni < 4; ni++)
                    mma16(c[mi][ni], a[mi], b[ni]);
        }
        s++; if (s == NSTG) s = 0;
    }

    // epilogue
    #pragma unroll
    for (int mi = 0; mi < 4; mi++){
        #pragma unroll
        for (int ni = 0; ni < 4; ni++){
            int col = bn + wn + ni * 8 + tg * 2;
            float bx = bias[col], by = bias[col + 1];
            #pragma unroll
            for (int h = 0; h < 2; h++){
                int row = bm + wm + mi * 16 + g + h * 8;
                float v0 = c[mi][ni][h * 2 + 0] + bx;
                float v1 = c[mi][ni][h * 2 + 1] + by;
                if (act == 1){
                    v0 = 0.5f * v0 * (1.0f + erff(v0 * 0.7071067811865475f));
                    v1 = 0.5f * v1 * (1.0f + erff(v1 * 0.7071067811865475f));
                }
                size_t o = (size_t)row * ldc + col;
                if (outHalf){
                    *reinterpret_cast<__half2*>(Ch + o) =
                        __floats2half2_rn(v0, v1);
                } else {
                    if (res){ v0 += res[o]; v1 += res[o + 1]; }
                    *reinterpret_cast<float2*>(C + o) = make_float2(v0, v1);
                }
            }
        }
    }
}

// ---------------- rmsnorm (D=1024), fp16 out; silu optional ------------------
__global__ void rmsnorm_h(const float* __restrict__ x, int ldx,
                          const float* __restrict__ w,
                          __half* __restrict__ y, int silu)
{
    int row = blockIdx.x;
    float4 v = reinterpret_cast<const float4*>(x + (size_t)row * ldx)[threadIdx.x];
    float ss = v.x*v.x + v.y*v.y + v.z*v.z + v.w*v.w;
    ss = block_reduce_sum_256(ss);
    float scale = rsqrtf(ss * (1.0f / Dv) + EPSv);
    float4 wv = reinterpret_cast<const float4*>(w)[threadIdx.x];
    v.x *= scale * wv.x; v.y *= scale * wv.y; v.z *= scale * wv.z; v.w *= scale * wv.w;
    if (silu){
        v.x = v.x / (1.0f + expf(-v.x)); v.y = v.y / (1.0f + expf(-v.y));
        v.z = v.z / (1.0f + expf(-v.z)); v.w = v.w / (1.0f + expf(-v.w));
    }
    __half2* yp = reinterpret_cast<__half2*>(y + (size_t)row * Dv) + threadIdx.x * 2;
    yp[0] = __floats2half2_rn(v.x, v.y);
    yp[1] = __floats2half2_rn(v.z, v.w);
}

// final deter: rmsnorm(x + add) -> fp32 out
__global__ void rmsnorm_f(const float* __restrict__ x, int ldx,
                          const float* __restrict__ add,
                          const float* __restrict__ w,
                          float* __restrict__ y)
{
    int row = blockIdx.x;
    float4 v = reinterpret_cast<const float4*>(x + (size_t)row * ldx)[threadIdx.x];
    float4 a = reinterpret_cast<const float4*>(add + (size_t)row * Dv)[threadIdx.x];
    v.x += a.x; v.y += a.y; v.z += a.z; v.w += a.w;
    float ss = v.x*v.x + v.y*v.y + v.z*v.z + v.w*v.w;
    ss = block_reduce_sum_256(ss);
    float scale = rsqrtf(ss * (1.0f / Dv) + EPSv);
    float4 wv = reinterpret_cast<const float4*>(w)[threadIdx.x];
    v.x *= scale * wv.x; v.y *= scale * wv.y; v.z *= scale * wv.z; v.w *= scale * wv.w;
    reinterpret_cast<float4*>(y + (size_t)row * Dv)[threadIdx.x] = v;
}

// ---------------- attention on packed fp16 QKV: one block per (b,h) ---------
__global__ void attn_k(const __half* __restrict__ QKV, const float* __restrict__ rel,
                       __half* __restrict__ O)
{
    __shared__ float qs[Sv][HDv], ks[Sv][HDv], vs[Sv][HDv], sc[Sv][Sv];
    int bh = blockIdx.x;
    int b = bh >> 3, h = bh & 7;
    size_t rowbase = (size_t)b * Sv * QKVN + (size_t)h * HDv;

    for (int e = threadIdx.x; e < Sv * 64; e += 256){
        int sI = e >> 6, d2 = e & 63;
        const __half* p = QKV + rowbase + (size_t)sI * QKVN + d2 * 2;
        float2 q2 = __half22float2(*reinterpret_cast<const __half2*>(p));
        float2 k2 = __half22float2(*reinterpret_cast<const __half2*>(p + Dv));
        float2 v2 = __half22float2(*reinterpret_cast<const __half2*>(p + 2*Dv));
        qs[sI][d2*2] = q2.x; qs[sI][d2*2+1] = q2.y;
        ks[sI][d2*2] = k2.x; ks[sI][d2*2+1] = k2.y;
        vs[sI][d2*2] = v2.x; vs[sI][d2*2+1] = v2.y;
    }
    __syncthreads();

    int lane = threadIdx.x & 31, warp = threadIdx.x >> 5;
    for (int e = warp; e < Sv * Sv; e += 8){
        int i = e / Sv, j = e % Sv;
        float p = 0.f;
        #pragma unroll
        for (int d = lane; d < HDv; d += 32) p += qs[i][d] * ks[j][d];
        #pragma unroll
        for (int o = 16; o; o >>= 1) p += __shfl_xor_sync(0xffffffffu, p, o);
        if (lane == 0){
            int r = i - j + Mclip;
            sc[i][j] = p * SCALEv + rel[r * Hv + h];
        }
    }
    __syncthreads();

    if (threadIdx.x < Sv){
        int i = threadIdx.x;
        float m = -1e30f;
        #pragma unroll
        for (int j = 0; j < Sv; j++) m = fmaxf(m, sc[i][j]);
        float s = 0.f;
        #pragma unroll
        for (int j = 0; j < Sv; j++){ float e_ = expf(sc[i][j] - m); sc[i][j] = e_; s += e_; }
        float inv = 1.0f / s;
        #pragma unroll
        for (int j = 0; j < Sv; j++) sc[i][j] *= inv;
    }
    __syncthreads();

    size_t obase = (size_t)b * Sv * Dv + (size_t)h * HDv;
    for (int e = threadIdx.x; e < Sv * 64; e += 256){
        int i = e >> 6, d2 = e & 63;
        int d = d2 * 2;
        float a0 = 0.f, a1 = 0.f;
        #pragma unroll
        for (int j = 0; j < Sv; j++){
            a0 += sc[i][j] * vs[j][d];
            a1 += sc[i][j] * vs[j][d+1];
        }
        *reinterpret_cast<__half2*>(O + obase + (size_t)i * Dv + d) =
            __floats2half2_rn(a0, a1);
    }
}

// ---------------- small data-movement kernels -------------------------------
__global__ void tokcat_k(const float* __restrict__ stoch, const float* __restrict__ action,
                         __half* __restrict__ out)
{
    int idx = blockIdx.x * blockDim.x + threadIdx.x;
    if (idx >= Bv * TOKCP) return;
    int b = idx / TOKCP, c = idx - b * TOKCP;
    float v;
    if (c < STOv) v = stoch[(size_t)b * STOv + c];
    else if (c < TOKC){ float a = action[(size_t)b * ACTv + (c - STOv)]; v = a / fmaxf(fabsf(a), 1.0f); }
    else v = 0.f;
    out[idx] = __float2half_rn(v);
}

__global__ void mem_in_k(const float* __restrict__ memory, float* __restrict__ seq)
{
    int idx = blockIdx.x * blockDim.x + threadIdx.x;
    if (idx >= Bv * MEMv * Dv / 4) return;
    int b = idx / (MEMv * Dv / 4);
    int r = idx - b * (MEMv * Dv / 4);
    reinterpret_cast<float4*>(seq + (size_t)b * Sv * Dv)[r] =
        reinterpret_cast<const float4*>(memory)[idx];
}

__global__ void mem_out_k(const float* __restrict__ seq, float* __restrict__ out)
{
    int idx = blockIdx.x * blockDim.x + threadIdx.x;
    if (idx >= Bv * MEMv * Dv / 4) return;
    int b = idx / (MEMv * Dv / 4);
    reinterpret_cast<float4*>(out)[idx] =
        reinterpret_cast<const float4*>(seq + (size_t)(b + 1) * Dv)[idx];  // seq[:,1:17,:]
}

// ---------------- driver ----------------------------------------------------
extern "C" void kernel_launch(void* const* d_in, const int* in_sizes, int n_in,
                              void* d_out, int out_size)
{
    (void)in_sizes; (void)n_in; (void)out_size;
    const float* stoch   = (const float*)d_in[0];
    const float* deter   = (const float*)d_in[1];
    const float* action  = (const float*)d_in[2];
    const float* memory  = (const float*)d_in[3];
    const float* inp_w1  = (const float*)d_in[4];
    const float* inp_b1  = (const float*)d_in[5];
    const float* inp_nw  = (const float*)d_in[6];
    const float* inp_w2  = (const float*)d_in[7];
    const float* inp_b2  = (const float*)d_in[8];
    const float* Wq      = (const float*)d_in[9];
    const float* bq      = (const float*)d_in[10];
    const float* Wk      = (const float*)d_in[11];
    const float* bk      = (const float*)d_in[12];
    const float* Wv      = (const float*)d_in[13];
    const float* bv      = (const float*)d_in[14];
    const float* Wo      = (const float*)d_in[15];
    const float* bo      = (const float*)d_in[16];
    const float* rel_emb = (const float*)d_in[17];
    const float* n1w     = (const float*)d_in[18];
    const float* n2w     = (const float*)d_in[19];
    const float* ffw1    = (const float*)d_in[20];
    const float* ffb1    = (const float*)d_in[21];
    const float* ffw2    = (const float*)d_in[22];
    const float* ffb2    = (const float*)d_in[23];
    const float* fnw     = (const float*)d_in[24];
    float* out = (float*)d_out;

    __half *p_tokcat, *p_hidh, *p_xn, *p_qkv, *p_att, *p_ff, *p_w;
    float *p_hid, *p_seq, *p_bqkv;
    cudaGetSymbolAddress((void**)&p_tokcat, g_tokcat);
    cudaGetSymbolAddress((void**)&p_hid,  g_hid);
    cudaGetSymbolAddress((void**)&p_hidh, g_hidh);
    cudaGetSymbolAddress((void**)&p_seq,  g_seq);
    cudaGetSymbolAddress((void**)&p_xn,   g_xn);
    cudaGetSymbolAddress((void**)&p_qkv,  g_qkv);
    cudaGetSymbolAddress((void**)&p_att,  g_att);
    cudaGetSymbolAddress((void**)&p_ff,   g_ff);
    cudaGetSymbolAddress((void**)&p_w,    g_w);
    cudaGetSymbolAddress((void**)&p_bqkv, g_bqkv);

    cudaFuncSetAttribute(gemm_h, cudaFuncAttributeMaxDynamicSharedMemorySize, GEMM_SMEMH);

    __half* w_inp1 = p_w + W_INP1_OFF;
    __half* w_inp2 = p_w + W_INP2_OFF;
    __half* w_qkv  = p_w + W_QKV_OFF;
    __half* w_o    = p_w + W_O_OFF;
    __half* w_f1   = p_w + W_F1_OFF;
    __half* w_f2   = p_w + W_F2_OFF;

    // ---- weight convert/transpose to fp16 [N][Kpad] ----
    auto wt = [&](const float* src, __half* dst, int Kin, int Kpad, int N){
        dim3 g(N/32, Kpad/32), b(32, 8);
        wcvt_h<<<g, b>>>(src, dst, Kin, Kpad, N);
    };
    wt(inp_w1, w_inp1, TOKC, TOKCP, HIDv);
    wt(inp_w2, w_inp2, HIDv, HIDv, Dv);
    for (int l = 0; l < Lv; l++){
        __half* dq = w_qkv + (size_t)l*QKVN*Dv;
        wt(Wq + (size_t)l*Dv*Dv, dq,                       Dv, Dv, Dv);
        wt(Wk + (size_t)l*Dv*Dv, dq + (size_t)Dv*Dv,       Dv, Dv, Dv);
        wt(Wv + (size_t)l*Dv*Dv, dq + (size_t)2*Dv*Dv,     Dv, Dv, Dv);
        wt(Wo   + (size_t)l*Dv*Dv, w_o  + (size_t)l*Dv*Dv, Dv, Dv, Dv);
        wt(ffw1 + (size_t)l*Dv*Fv, w_f1 + (size_t)l*Fv*Dv, Dv, Dv, Fv);
        wt(ffw2 + (size_t)l*Fv*Dv, w_f2 + (size_t)l*Dv*Fv, Fv, Fv, Dv);
    }
    packb_qkv_k<<<(Lv * QKVN + 255) / 256, 256>>>(bq, bk, bv, p_bqkv);

    // prep
    tokcat_k<<<(Bv * TOKCP + 255) / 256, 256>>>(stoch, action, p_tokcat);
    mem_in_k<<<(Bv * MEMv * Dv / 4 + 255) / 256, 256>>>(memory, p_seq);

    // input MLP
    dim3 gI(HIDv / BNh, Bv / BMh);         // 8 x 16
    gemm_h<<<gI, 256, GEMM_SMEMH>>>(p_tokcat, w_inp1, inp_b1, nullptr, p_hid, nullptr,
                                    Bv, HIDv, TOKCP, TOKCP, HIDv, 0, 0);
    rmsnorm_h<<<Bv, 256>>>(p_hid, Dv, inp_nw, p_hidh, 1);
    gemm_h<<<gI, 256, GEMM_SMEMH>>>(p_hidh, w_inp2, inp_b2, nullptr,
                                    p_seq + (size_t)MEMv * Dv, nullptr,
                                    Bv, Dv, HIDv, HIDv, Sv * Dv, 0, 0);

    dim3 gQ(QKVN / BNh, NTOK / BMh);       // 24 x 272
    dim3 gP(Dv / BNh, NTOK / BMh);         // 8 x 272
    dim3 gF(Fv / BNh, NTOK / BMh);         // 32 x 272

    for (int l = 0; l < Lv; l++){
        const __half* wqkv = w_qkv + (size_t)l * QKVN * Dv;
        const __half* wo   = w_o   + (size_t)l * Dv * Dv;
        const __half* f1   = w_f1  + (size_t)l * Fv * Dv;
        const __half* f2   = w_f2  + (size_t)l * Dv * Fv;

        rmsnorm_h<<<NTOK, 256>>>(p_seq, Dv, n1w + l * Dv, p_xn, 0);
        gemm_h<<<gQ, 256, GEMM_SMEMH>>>(p_xn, wqkv, p_bqkv + l * QKVN, nullptr,
                                        nullptr, p_qkv, NTOK, QKVN, Dv, Dv, QKVN, 0, 1);
        attn_k<<<Bv * Hv, 256>>>(p_qkv, rel_emb + (size_t)l * (2 * Mclip + 1) * Hv, p_att);
        gemm_h<<<gP, 256, GEMM_SMEMH>>>(p_att, wo, bo + l * Dv, p_seq,
                                        p_seq, nullptr, NTOK, Dv, Dv, Dv, Dv, 0, 0);
        rmsnorm_h<<<NTOK, 256>>>(p_seq, Dv, n2w + l * Dv, p_xn, 0);
        gemm_h<<<gF, 256, GEMM_SMEMH>>>(p_xn, f1, ffb1 + l * Fv, nullptr,
                                        nullptr, p_ff, NTOK, Fv, Dv, Dv, Fv, 1, 1);
        gemm_h<<<gP, 256, GEMM_SMEMH>>>(p_ff, f2, ffb2 + l * Dv, p_seq,
                                        p_seq, nullptr, NTOK, Dv, Fv, Fv, Dv, 0, 0);
    }

    // new_deter = rmsnorm(seq[:, -1] + deter, fnw)  -> out[0 : B*D)
    rmsnorm_f<<<Bv, 256>>>(p_seq + (size_t)MEMv * Dv, Sv * Dv, deter, fnw, out);
    // new_mem = seq[:, 1:17]  -> out[B*D : ]
    mem_out_k<<<(Bv * MEMv * Dv / 4 + 255) / 256, 256>>>(p_seq, out + (size_t)Bv * Dv);
}